// round 1
// baseline (speedup 1.0000x reference)
#include <cuda_runtime.h>

// QFNetBlock: state = normalize(x.reshape(B,D)); 4 complex GEMM layers with
// CNOT-chain permutation after layers 0 and 2; output = |state|.
// B=256, D=4096 (n_wires=12).

#define DD 4096
#define BB 256
#define NW 12

#define BM 64
#define BN 128
#define BK 16

// Ping-pong complex state scratch (B*D floats each = 4 MB, total 16 MB).
__device__ float g_r0[BB * DD];
__device__ float g_i0[BB * DD];
__device__ float g_r1[BB * DD];
__device__ float g_i1[BB * DD];

// ---------------------------------------------------------------------------
// Row L2-normalize: sr[b, :] = x[b, :] / ||x[b, :]||
// ---------------------------------------------------------------------------
__global__ void normalize_kernel(const float* __restrict__ x,
                                 float* __restrict__ sr) {
    const int b = blockIdx.x;
    const float4* xv = reinterpret_cast<const float4*>(x + (size_t)b * DD);
    float ss = 0.f;
#pragma unroll 4
    for (int i = threadIdx.x; i < DD / 4; i += blockDim.x) {
        float4 v = xv[i];
        ss += v.x * v.x + v.y * v.y + v.z * v.z + v.w * v.w;
    }
    __shared__ float red[256];
    red[threadIdx.x] = ss;
    __syncthreads();
    for (int s = 128; s > 0; s >>= 1) {
        if (threadIdx.x < s) red[threadIdx.x] += red[threadIdx.x + s];
        __syncthreads();
    }
    const float inv = rsqrtf(red[0]);
    float4* ov = reinterpret_cast<float4*>(sr + (size_t)b * DD);
    for (int i = threadIdx.x; i < DD / 4; i += blockDim.x) {
        float4 v = xv[i];
        v.x *= inv; v.y *= inv; v.z *= inv; v.w *= inv;
        ov[i] = v;
    }
}

// ---------------------------------------------------------------------------
// Fused complex GEMM:
//   Or[b, i] = sum_k Ur[i,k]*Sr[b,k] - Ui[i,k]*Si[b,k]
//   Oi[b, i] = sum_k Ur[i,k]*Si[b,k] + Ui[i,k]*Sr[b,k]
// CPLX=false: Si == 0  =>  Or = Ur*Sr, Oi = Ui*Sr  (layer-0 real input).
// Tiles: BM=64 (i), BN=128 (b), BK=16. 256 threads, thread tile 4(m) x 8(n).
// ---------------------------------------------------------------------------
template <bool CPLX>
__global__ void __launch_bounds__(256)
cgemm_kernel(const float* __restrict__ Ur, const float* __restrict__ Ui,
             const float* __restrict__ Sr, const float* __restrict__ Si,
             float* __restrict__ Or, float* __restrict__ Oi) {
    __shared__ __align__(16) float Asr[BK][BM + 4];
    __shared__ __align__(16) float Asi[BK][BM + 4];
    __shared__ __align__(16) float Bsr[BK][BN + 4];
    __shared__ __align__(16) float Bsi[BK][BN + 4];

    const int tid   = threadIdx.x;
    const int ibase = blockIdx.x * BM;   // output row block (i)
    const int bbase = blockIdx.y * BN;   // batch block (b)

    // Loader mapping: 4 threads per row, each thread a float4 of k.
    const int lrow = tid >> 2;           // 0..63
    const int lk   = (tid & 3) << 2;     // 0,4,8,12

    const float* pUr  = Ur + (size_t)(ibase + lrow) * DD + lk;
    const float* pUi  = Ui + (size_t)(ibase + lrow) * DD + lk;
    const float* pSr0 = Sr + (size_t)(bbase + lrow) * DD + lk;
    const float* pSr1 = Sr + (size_t)(bbase + lrow + 64) * DD + lk;
    const float* pSi0 = Si + (size_t)(bbase + lrow) * DD + lk;
    const float* pSi1 = Si + (size_t)(bbase + lrow + 64) * DD + lk;

    const int tx = tid & 15;             // m group (4 rows each)
    const int ty = tid >> 4;             // n group (8 cols each)

    float accR[4][8];
    float accI[4][8];
#pragma unroll
    for (int m = 0; m < 4; ++m)
#pragma unroll
        for (int n = 0; n < 8; ++n) { accR[m][n] = 0.f; accI[m][n] = 0.f; }

    // Prologue: stage k-block 0 into registers.
    float4 ur4  = *reinterpret_cast<const float4*>(pUr);
    float4 ui4  = *reinterpret_cast<const float4*>(pUi);
    float4 sr40 = *reinterpret_cast<const float4*>(pSr0);
    float4 sr41 = *reinterpret_cast<const float4*>(pSr1);
    float4 si40, si41;
    if (CPLX) {
        si40 = *reinterpret_cast<const float4*>(pSi0);
        si41 = *reinterpret_cast<const float4*>(pSi1);
    }

    const int KT = DD / BK;  // 256
    for (int kt = 0; kt < KT; ++kt) {
        // Commit staged registers to SMEM (transposed to [k][row]).
        Asr[lk + 0][lrow] = ur4.x; Asr[lk + 1][lrow] = ur4.y;
        Asr[lk + 2][lrow] = ur4.z; Asr[lk + 3][lrow] = ur4.w;
        Asi[lk + 0][lrow] = ui4.x; Asi[lk + 1][lrow] = ui4.y;
        Asi[lk + 2][lrow] = ui4.z; Asi[lk + 3][lrow] = ui4.w;
        Bsr[lk + 0][lrow] = sr40.x; Bsr[lk + 1][lrow] = sr40.y;
        Bsr[lk + 2][lrow] = sr40.z; Bsr[lk + 3][lrow] = sr40.w;
        Bsr[lk + 0][lrow + 64] = sr41.x; Bsr[lk + 1][lrow + 64] = sr41.y;
        Bsr[lk + 2][lrow + 64] = sr41.z; Bsr[lk + 3][lrow + 64] = sr41.w;
        if (CPLX) {
            Bsi[lk + 0][lrow] = si40.x; Bsi[lk + 1][lrow] = si40.y;
            Bsi[lk + 2][lrow] = si40.z; Bsi[lk + 3][lrow] = si40.w;
            Bsi[lk + 0][lrow + 64] = si41.x; Bsi[lk + 1][lrow + 64] = si41.y;
            Bsi[lk + 2][lrow + 64] = si41.z; Bsi[lk + 3][lrow + 64] = si41.w;
        }
        __syncthreads();

        // Prefetch next k-block while computing this one.
        if (kt + 1 < KT) {
            const int off = (kt + 1) * BK;
            ur4  = *reinterpret_cast<const float4*>(pUr + off);
            ui4  = *reinterpret_cast<const float4*>(pUi + off);
            sr40 = *reinterpret_cast<const float4*>(pSr0 + off);
            sr41 = *reinterpret_cast<const float4*>(pSr1 + off);
            if (CPLX) {
                si40 = *reinterpret_cast<const float4*>(pSi0 + off);
                si41 = *reinterpret_cast<const float4*>(pSi1 + off);
            }
        }

#pragma unroll
        for (int k = 0; k < BK; ++k) {
            float4 a_r  = *reinterpret_cast<const float4*>(&Asr[k][tx * 4]);
            float4 a_i  = *reinterpret_cast<const float4*>(&Asi[k][tx * 4]);
            float4 b_r0 = *reinterpret_cast<const float4*>(&Bsr[k][ty * 8]);
            float4 b_r1 = *reinterpret_cast<const float4*>(&Bsr[k][ty * 8 + 4]);
            const float arv[4] = {a_r.x, a_r.y, a_r.z, a_r.w};
            const float aiv[4] = {a_i.x, a_i.y, a_i.z, a_i.w};
            const float brv[8] = {b_r0.x, b_r0.y, b_r0.z, b_r0.w,
                                  b_r1.x, b_r1.y, b_r1.z, b_r1.w};
            if (CPLX) {
                float4 b_i0 = *reinterpret_cast<const float4*>(&Bsi[k][ty * 8]);
                float4 b_i1 = *reinterpret_cast<const float4*>(&Bsi[k][ty * 8 + 4]);
                const float biv[8] = {b_i0.x, b_i0.y, b_i0.z, b_i0.w,
                                      b_i1.x, b_i1.y, b_i1.z, b_i1.w};
#pragma unroll
                for (int m = 0; m < 4; ++m)
#pragma unroll
                    for (int n = 0; n < 8; ++n) {
                        accR[m][n] += arv[m] * brv[n];
                        accR[m][n] -= aiv[m] * biv[n];
                        accI[m][n] += arv[m] * biv[n];
                        accI[m][n] += aiv[m] * brv[n];
                    }
            } else {
#pragma unroll
                for (int m = 0; m < 4; ++m)
#pragma unroll
                    for (int n = 0; n < 8; ++n) {
                        accR[m][n] += arv[m] * brv[n];
                        accI[m][n] += aiv[m] * brv[n];
                    }
            }
        }
        __syncthreads();
    }

    // Epilogue: write new state in (B, D) row-major layout (coalesced float4).
#pragma unroll
    for (int n = 0; n < 8; ++n) {
        const size_t row = (size_t)(bbase + ty * 8 + n) * DD + ibase + tx * 4;
        float4 vr = make_float4(accR[0][n], accR[1][n], accR[2][n], accR[3][n]);
        float4 vi = make_float4(accI[0][n], accI[1][n], accI[2][n], accI[3][n]);
        *reinterpret_cast<float4*>(Or + row) = vr;
        *reinterpret_cast<float4*>(Oi + row) = vi;
    }
}

// ---------------------------------------------------------------------------
// CNOT-chain permutation: out[b, j] = in[b, perm(j)], where
// perm(j) = p_0(p_1(...p_{NW-1}(j)...)),  p_i: if bit(NW-1-i) set,
// flip bit(NW-1-((i+1)%NW)).
// ---------------------------------------------------------------------------
__global__ void perm_kernel(const float* __restrict__ inr,
                            const float* __restrict__ ini,
                            float* __restrict__ outr,
                            float* __restrict__ outi) {
    const int idx = blockIdx.x * blockDim.x + threadIdx.x;
    const int b = idx >> 12;
    const int j = idx & (DD - 1);
    int m = j;
#pragma unroll
    for (int i = NW - 1; i >= 0; --i) {
        const int c = NW - 1 - i;
        const int t = NW - 1 - ((i + 1) % NW);
        m ^= ((m >> c) & 1) << t;
    }
    const size_t src = ((size_t)b << 12) + m;
    outr[idx] = inr[src];
    outi[idx] = ini[src];
}

// ---------------------------------------------------------------------------
// |z| epilogue
// ---------------------------------------------------------------------------
__global__ void abs_kernel(const float* __restrict__ re,
                           const float* __restrict__ im,
                           float* __restrict__ out) {
    const int idx = blockIdx.x * blockDim.x + threadIdx.x;
    const float r = re[idx];
    const float i = im[idx];
    out[idx] = sqrtf(r * r + i * i);
}

// ---------------------------------------------------------------------------
extern "C" void kernel_launch(void* const* d_in, const int* in_sizes, int n_in,
                              void* d_out, int out_size) {
    const float* x   = (const float*)d_in[0];
    const float* u0r = (const float*)d_in[1];
    const float* u0i = (const float*)d_in[2];
    const float* u1r = (const float*)d_in[3];
    const float* u1i = (const float*)d_in[4];
    const float* u2r = (const float*)d_in[5];
    const float* u2i = (const float*)d_in[6];
    const float* u3r = (const float*)d_in[7];
    const float* u3i = (const float*)d_in[8];
    float* out = (float*)d_out;

    float *r0, *i0, *r1, *i1;
    cudaGetSymbolAddress((void**)&r0, g_r0);
    cudaGetSymbolAddress((void**)&i0, g_i0);
    cudaGetSymbolAddress((void**)&r1, g_r1);
    cudaGetSymbolAddress((void**)&i1, g_i1);

    const dim3 gg(DD / BM, BB / BN);   // (64, 2) = 128 CTAs
    const int elems = BB * DD;

    // state (real) -> r0
    normalize_kernel<<<BB, 256>>>(x, r0);
    // layer 0 (real input): (r1, i1) = U0 * r0
    cgemm_kernel<false><<<gg, 256>>>(u0r, u0i, r0, r0, r1, i1);
    // permutation: (r0, i0) = perm(r1, i1)
    perm_kernel<<<elems / 256, 256>>>(r1, i1, r0, i0);
    // layer 1: (r1, i1) = U1 * (r0, i0)
    cgemm_kernel<true><<<gg, 256>>>(u1r, u1i, r0, i0, r1, i1);
    // layer 2: (r0, i0) = U2 * (r1, i1)
    cgemm_kernel<true><<<gg, 256>>>(u2r, u2i, r1, i1, r0, i0);
    // permutation: (r1, i1) = perm(r0, i0)
    perm_kernel<<<elems / 256, 256>>>(r0, i0, r1, i1);
    // layer 3: (r0, i0) = U3 * (r1, i1)
    cgemm_kernel<true><<<gg, 256>>>(u3r, u3i, r1, i1, r0, i0);
    // |state| -> output (B, S, E) == (B, D) row-major
    abs_kernel<<<elems / 256, 256>>>(r0, i0, out);
}

// round 3
// speedup vs baseline: 2.0141x; 2.0141x over previous
#include <cuda_runtime.h>
#include <cuda_bf16.h>
#include <cstdint>

// QFNetBlock: normalize -> 4 complex GEMM layers (CNOT perm after 0,2) -> abs.
// B=256, D=4096. Complex GEMM via mma.sync bf16 (3x split, fp32 accum).
// NOTE: harness compiles via compute_103 (no 'a') -> tcgen05 unavailable; use HMMA.

#define DD 4096
#define BB 256
#define NW 12

#define KC 16             // k per chunk (one m16n8k16 step)
#define NCHUNK (DD / KC)  // 256
#define SROW 24           // smem row stride in bf16 (48B -> conflict-free frag loads)

// Ping-pong complex state scratch (4 MB each).
__device__ float g_r0[BB * DD];
__device__ float g_i0[BB * DD];
__device__ float g_r1[BB * DD];
__device__ float g_i1[BB * DD];

// f32 -> (bf16 hi, bf16 lo) pairwise pack into two uint32 (2x bf16 each)
__device__ __forceinline__ void cvt_hilo2(float a, float b, uint32_t& hi, uint32_t& lo) {
    __nv_bfloat16 ha = __float2bfloat16_rn(a);
    __nv_bfloat16 hb = __float2bfloat16_rn(b);
    __nv_bfloat16 la = __float2bfloat16_rn(a - __bfloat162float(ha));
    __nv_bfloat16 lb = __float2bfloat16_rn(b - __bfloat162float(hb));
    __nv_bfloat162 h2 = __halves2bfloat162(ha, hb);
    __nv_bfloat162 l2 = __halves2bfloat162(la, lb);
    hi = *reinterpret_cast<uint32_t*>(&h2);
    lo = *reinterpret_cast<uint32_t*>(&l2);
}

#define MMA(C, A, B)                                                           \
    asm volatile(                                                              \
        "mma.sync.aligned.m16n8k16.row.col.f32.bf16.bf16.f32 "                 \
        "{%0,%1,%2,%3}, {%4,%5,%6,%7}, {%8,%9}, {%0,%1,%2,%3};"                \
        : "+f"((C)[0]), "+f"((C)[1]), "+f"((C)[2]), "+f"((C)[3])               \
        : "r"((A)[0]), "r"((A)[1]), "r"((A)[2]), "r"((A)[3]),                  \
          "r"((B)[0]), "r"((B)[1]))

// ---------------------------------------------------------------------------
// Complex GEMM: O[b,i] = sum_k U[i,k] * S[b,k]  (complex, bf16x3 split)
// CTA tile: M=64 (batch b), N=128 (row i). 8 warps: 2(M) x 4(N), warp 32x32.
// grid (DD/128=32, BB/64=4) = 128 CTAs, 256 threads.
// ---------------------------------------------------------------------------
template <bool CPLX>
__global__ void __launch_bounds__(256, 1)
cgemm_mma(const float* __restrict__ Ur, const float* __restrict__ Ui,
          const float* __restrict__ Sr, const float* __restrict__ Si,
          float* __restrict__ Or, float* __restrict__ Oi) {
    // smem: A tiles (S): 4 x [64][SROW], B tiles (U): 4 x [128][SROW]
    __shared__ __align__(16) __nv_bfloat16 sm[(4 * 64 + 4 * 128) * SROW];
    __nv_bfloat16* sSrH = sm;
    __nv_bfloat16* sSrL = sSrH + 64 * SROW;
    __nv_bfloat16* sSiH = sSrL + 64 * SROW;
    __nv_bfloat16* sSiL = sSiH + 64 * SROW;
    __nv_bfloat16* sUrH = sSiL + 64 * SROW;
    __nv_bfloat16* sUrL = sUrH + 128 * SROW;
    __nv_bfloat16* sUiH = sUrL + 128 * SROW;
    __nv_bfloat16* sUiL = sUiH + 128 * SROW;

    const int tid = threadIdx.x;
    const int wid = tid >> 5;
    const int lane = tid & 31;
    const int ibase = blockIdx.x * 128;   // N (U rows / output column i)
    const int bbase = blockIdx.y * 64;    // M (batch)

    // ---- loader mapping ----
    const int arow = tid >> 2;            // 0..63
    const int akp  = (tid & 3) << 2;      // 0,4,8,12

    const float* pSr = Sr + (size_t)(bbase + arow) * DD + akp;
    const float* pSi = Si + (size_t)(bbase + arow) * DD + akp;
    const float* pUr0 = Ur + (size_t)(ibase + arow) * DD + akp;
    const float* pUr1 = Ur + (size_t)(ibase + arow + 64) * DD + akp;
    const float* pUi0 = Ui + (size_t)(ibase + arow) * DD + akp;
    const float* pUi1 = Ui + (size_t)(ibase + arow + 64) * DD + akp;

    // ---- compute mapping ----
    const int warp_m = wid & 1;           // 0..1
    const int warp_n = wid >> 1;          // 0..3
    const int lrow = lane >> 2;           // 0..7
    const int lcol2 = (lane & 3) << 1;    // 0,2,4,6 (bf16 col)

    float cR[2][4][4];
    float cI[2][4][4];
#pragma unroll
    for (int m = 0; m < 2; ++m)
#pragma unroll
        for (int n = 0; n < 4; ++n)
#pragma unroll
            for (int r = 0; r < 4; ++r) { cR[m][n][r] = 0.f; cI[m][n][r] = 0.f; }

    // Prologue: stage chunk 0.
    float4 v_sr = *reinterpret_cast<const float4*>(pSr);
    float4 v_si;
    if (CPLX) v_si = *reinterpret_cast<const float4*>(pSi);
    float4 v_ur0 = *reinterpret_cast<const float4*>(pUr0);
    float4 v_ur1 = *reinterpret_cast<const float4*>(pUr1);
    float4 v_ui0 = *reinterpret_cast<const float4*>(pUi0);
    float4 v_ui1 = *reinterpret_cast<const float4*>(pUi1);

#pragma unroll 1
    for (int c = 0; c < NCHUNK; ++c) {
        // ---- commit staged regs to smem (converted hi/lo) ----
        {
            uint32_t h0, l0, h1, l1;
            cvt_hilo2(v_sr.x, v_sr.y, h0, l0);
            cvt_hilo2(v_sr.z, v_sr.w, h1, l1);
            *reinterpret_cast<uint2*>(sSrH + arow * SROW + akp) = make_uint2(h0, h1);
            *reinterpret_cast<uint2*>(sSrL + arow * SROW + akp) = make_uint2(l0, l1);
            if (CPLX) {
                cvt_hilo2(v_si.x, v_si.y, h0, l0);
                cvt_hilo2(v_si.z, v_si.w, h1, l1);
                *reinterpret_cast<uint2*>(sSiH + arow * SROW + akp) = make_uint2(h0, h1);
                *reinterpret_cast<uint2*>(sSiL + arow * SROW + akp) = make_uint2(l0, l1);
            }
            cvt_hilo2(v_ur0.x, v_ur0.y, h0, l0);
            cvt_hilo2(v_ur0.z, v_ur0.w, h1, l1);
            *reinterpret_cast<uint2*>(sUrH + arow * SROW + akp) = make_uint2(h0, h1);
            *reinterpret_cast<uint2*>(sUrL + arow * SROW + akp) = make_uint2(l0, l1);
            cvt_hilo2(v_ur1.x, v_ur1.y, h0, l0);
            cvt_hilo2(v_ur1.z, v_ur1.w, h1, l1);
            *reinterpret_cast<uint2*>(sUrH + (arow + 64) * SROW + akp) = make_uint2(h0, h1);
            *reinterpret_cast<uint2*>(sUrL + (arow + 64) * SROW + akp) = make_uint2(l0, l1);
            cvt_hilo2(v_ui0.x, v_ui0.y, h0, l0);
            cvt_hilo2(v_ui0.z, v_ui0.w, h1, l1);
            *reinterpret_cast<uint2*>(sUiH + arow * SROW + akp) = make_uint2(h0, h1);
            *reinterpret_cast<uint2*>(sUiL + arow * SROW + akp) = make_uint2(l0, l1);
            cvt_hilo2(v_ui1.x, v_ui1.y, h0, l0);
            cvt_hilo2(v_ui1.z, v_ui1.w, h1, l1);
            *reinterpret_cast<uint2*>(sUiH + (arow + 64) * SROW + akp) = make_uint2(h0, h1);
            *reinterpret_cast<uint2*>(sUiL + (arow + 64) * SROW + akp) = make_uint2(l0, l1);
        }
        __syncthreads();

        // ---- prefetch next chunk ----
        if (c + 1 < NCHUNK) {
            const int off = (c + 1) * KC;
            v_sr = *reinterpret_cast<const float4*>(pSr + off);
            if (CPLX) v_si = *reinterpret_cast<const float4*>(pSi + off);
            v_ur0 = *reinterpret_cast<const float4*>(pUr0 + off);
            v_ur1 = *reinterpret_cast<const float4*>(pUr1 + off);
            v_ui0 = *reinterpret_cast<const float4*>(pUi0 + off);
            v_ui1 = *reinterpret_cast<const float4*>(pUi1 + off);
        }

        // ---- load fragments ----
        uint32_t a_srh[2][4], a_srl[2][4];
        uint32_t a_sih[2][4], a_sil[2][4], a_sihn[2][4], a_siln[2][4];
#pragma unroll
        for (int m = 0; m < 2; ++m) {
            const int r0 = (warp_m * 32 + m * 16 + lrow) * SROW;
            const int r8 = r0 + 8 * SROW;
            a_srh[m][0] = *reinterpret_cast<const uint32_t*>(sSrH + r0 + lcol2);
            a_srh[m][1] = *reinterpret_cast<const uint32_t*>(sSrH + r8 + lcol2);
            a_srh[m][2] = *reinterpret_cast<const uint32_t*>(sSrH + r0 + lcol2 + 8);
            a_srh[m][3] = *reinterpret_cast<const uint32_t*>(sSrH + r8 + lcol2 + 8);
            a_srl[m][0] = *reinterpret_cast<const uint32_t*>(sSrL + r0 + lcol2);
            a_srl[m][1] = *reinterpret_cast<const uint32_t*>(sSrL + r8 + lcol2);
            a_srl[m][2] = *reinterpret_cast<const uint32_t*>(sSrL + r0 + lcol2 + 8);
            a_srl[m][3] = *reinterpret_cast<const uint32_t*>(sSrL + r8 + lcol2 + 8);
            if (CPLX) {
                a_sih[m][0] = *reinterpret_cast<const uint32_t*>(sSiH + r0 + lcol2);
                a_sih[m][1] = *reinterpret_cast<const uint32_t*>(sSiH + r8 + lcol2);
                a_sih[m][2] = *reinterpret_cast<const uint32_t*>(sSiH + r0 + lcol2 + 8);
                a_sih[m][3] = *reinterpret_cast<const uint32_t*>(sSiH + r8 + lcol2 + 8);
                a_sil[m][0] = *reinterpret_cast<const uint32_t*>(sSiL + r0 + lcol2);
                a_sil[m][1] = *reinterpret_cast<const uint32_t*>(sSiL + r8 + lcol2);
                a_sil[m][2] = *reinterpret_cast<const uint32_t*>(sSiL + r0 + lcol2 + 8);
                a_sil[m][3] = *reinterpret_cast<const uint32_t*>(sSiL + r8 + lcol2 + 8);
#pragma unroll
                for (int r = 0; r < 4; ++r) {
                    a_sihn[m][r] = a_sih[m][r] ^ 0x80008000u;
                    a_siln[m][r] = a_sil[m][r] ^ 0x80008000u;
                }
            }
        }
        uint32_t b_urh[4][2], b_url[4][2], b_uih[4][2], b_uil[4][2];
#pragma unroll
        for (int n = 0; n < 4; ++n) {
            const int r = (warp_n * 32 + n * 8 + lrow) * SROW;
            b_urh[n][0] = *reinterpret_cast<const uint32_t*>(sUrH + r + lcol2);
            b_urh[n][1] = *reinterpret_cast<const uint32_t*>(sUrH + r + lcol2 + 8);
            b_url[n][0] = *reinterpret_cast<const uint32_t*>(sUrL + r + lcol2);
            b_url[n][1] = *reinterpret_cast<const uint32_t*>(sUrL + r + lcol2 + 8);
            b_uih[n][0] = *reinterpret_cast<const uint32_t*>(sUiH + r + lcol2);
            b_uih[n][1] = *reinterpret_cast<const uint32_t*>(sUiH + r + lcol2 + 8);
            b_uil[n][0] = *reinterpret_cast<const uint32_t*>(sUiL + r + lcol2);
            b_uil[n][1] = *reinterpret_cast<const uint32_t*>(sUiL + r + lcol2 + 8);
        }

        // ---- MMAs ----
#pragma unroll
        for (int m = 0; m < 2; ++m) {
#pragma unroll
            for (int n = 0; n < 4; ++n) {
                // C_R += SrH*UrH + SrL*UrH + SrH*UrL
                MMA(cR[m][n], a_srh[m], b_urh[n]);
                MMA(cR[m][n], a_srl[m], b_urh[n]);
                MMA(cR[m][n], a_srh[m], b_url[n]);
                // C_I += SrH*UiH + SrL*UiH + SrH*UiL
                MMA(cI[m][n], a_srh[m], b_uih[n]);
                MMA(cI[m][n], a_srl[m], b_uih[n]);
                MMA(cI[m][n], a_srh[m], b_uil[n]);
                if (CPLX) {
                    // C_R -= Si*Ui  (negated Si frags)
                    MMA(cR[m][n], a_sihn[m], b_uih[n]);
                    MMA(cR[m][n], a_siln[m], b_uih[n]);
                    MMA(cR[m][n], a_sihn[m], b_uil[n]);
                    // C_I += Si*Ur
                    MMA(cI[m][n], a_sih[m], b_urh[n]);
                    MMA(cI[m][n], a_sil[m], b_urh[n]);
                    MMA(cI[m][n], a_sih[m], b_url[n]);
                }
            }
        }
        __syncthreads();
    }

    // ---- epilogue: C fragment layout -> (B, D) row-major ----
#pragma unroll
    for (int m = 0; m < 2; ++m) {
#pragma unroll
        for (int n = 0; n < 4; ++n) {
            const int brow = bbase + warp_m * 32 + m * 16 + lrow;
            const int icol = ibase + warp_n * 32 + n * 8 + lcol2;
            float2* pr0 = reinterpret_cast<float2*>(Or + (size_t)brow * DD + icol);
            float2* pr8 = reinterpret_cast<float2*>(Or + (size_t)(brow + 8) * DD + icol);
            float2* pi0 = reinterpret_cast<float2*>(Oi + (size_t)brow * DD + icol);
            float2* pi8 = reinterpret_cast<float2*>(Oi + (size_t)(brow + 8) * DD + icol);
            *pr0 = make_float2(cR[m][n][0], cR[m][n][1]);
            *pr8 = make_float2(cR[m][n][2], cR[m][n][3]);
            *pi0 = make_float2(cI[m][n][0], cI[m][n][1]);
            *pi8 = make_float2(cI[m][n][2], cI[m][n][3]);
        }
    }
}

// ---------------------------------------------------------------------------
__global__ void normalize_kernel(const float* __restrict__ x, float* __restrict__ sr) {
    const int b = blockIdx.x;
    const float4* xv = reinterpret_cast<const float4*>(x + (size_t)b * DD);
    float ss = 0.f;
#pragma unroll 4
    for (int i = threadIdx.x; i < DD / 4; i += blockDim.x) {
        float4 v = xv[i];
        ss += v.x * v.x + v.y * v.y + v.z * v.z + v.w * v.w;
    }
    __shared__ float red[256];
    red[threadIdx.x] = ss;
    __syncthreads();
    for (int s = 128; s > 0; s >>= 1) {
        if (threadIdx.x < s) red[threadIdx.x] += red[threadIdx.x + s];
        __syncthreads();
    }
    const float inv = rsqrtf(red[0]);
    float4* ov = reinterpret_cast<float4*>(sr + (size_t)b * DD);
    for (int i = threadIdx.x; i < DD / 4; i += blockDim.x) {
        float4 v = xv[i];
        v.x *= inv; v.y *= inv; v.z *= inv; v.w *= inv;
        ov[i] = v;
    }
}

__global__ void perm_kernel(const float* __restrict__ inr, const float* __restrict__ ini,
                            float* __restrict__ outr, float* __restrict__ outi) {
    const int idx = blockIdx.x * blockDim.x + threadIdx.x;
    const int b = idx >> 12;
    const int j = idx & (DD - 1);
    int m = j;
#pragma unroll
    for (int i = NW - 1; i >= 0; --i) {
        const int cc = NW - 1 - i;
        const int t = NW - 1 - ((i + 1) % NW);
        m ^= ((m >> cc) & 1) << t;
    }
    const size_t src = ((size_t)b << 12) + m;
    outr[idx] = inr[src];
    outi[idx] = ini[src];
}

__global__ void abs_kernel(const float* __restrict__ re, const float* __restrict__ im,
                           float* __restrict__ out) {
    const int idx = blockIdx.x * blockDim.x + threadIdx.x;
    const float r = re[idx];
    const float i = im[idx];
    out[idx] = sqrtf(r * r + i * i);
}

// ---------------------------------------------------------------------------
extern "C" void kernel_launch(void* const* d_in, const int* in_sizes, int n_in,
                              void* d_out, int out_size) {
    const float* x   = (const float*)d_in[0];
    const float* u0r = (const float*)d_in[1];
    const float* u0i = (const float*)d_in[2];
    const float* u1r = (const float*)d_in[3];
    const float* u1i = (const float*)d_in[4];
    const float* u2r = (const float*)d_in[5];
    const float* u2i = (const float*)d_in[6];
    const float* u3r = (const float*)d_in[7];
    const float* u3i = (const float*)d_in[8];
    float* out = (float*)d_out;

    float *r0, *i0, *r1, *i1;
    cudaGetSymbolAddress((void**)&r0, g_r0);
    cudaGetSymbolAddress((void**)&i0, g_i0);
    cudaGetSymbolAddress((void**)&r1, g_r1);
    cudaGetSymbolAddress((void**)&i1, g_i1);

    const dim3 gg(DD / 128, BB / 64);  // (32, 4) = 128 CTAs
    const int elems = BB * DD;

    normalize_kernel<<<BB, 256>>>(x, r0);
    cgemm_mma<false><<<gg, 256>>>(u0r, u0i, r0, r0, r1, i1);
    perm_kernel<<<elems / 256, 256>>>(r1, i1, r0, i0);
    cgemm_mma<true><<<gg, 256>>>(u1r, u1i, r0, i0, r1, i1);
    cgemm_mma<true><<<gg, 256>>>(u2r, u2i, r1, i1, r0, i0);
    perm_kernel<<<elems / 256, 256>>>(r0, i0, r1, i1);
    cgemm_mma<true><<<gg, 256>>>(u3r, u3i, r1, i1, r0, i0);
    abs_kernel<<<elems / 256, 256>>>(r0, i0, out);
}